// round 16
// baseline (speedup 1.0000x reference)
#include <cuda_runtime.h>
#include <cuda_fp16.h>
#include <cstdint>

// ---------------------------------------------------------------------------
// x_{k+1}[v] = relu( sum_d W[v,d]*x_k[src[v,d]] - demand[v] ), 32 iters,
// out = weights * x_32.  B=4, N=100K, D=16 (12 valid).
//
// R16 = R15 + SPLIT-HALF staging overlap: two cp.async.bulk (H0/H1, two
// mbarriers). Walk runs twice, predicated per edge on (idx < h0) /
// (idx >= h0) — rows stay warp-uniform (coalesced edge regs already
// prefetched), predication costs issue slots only. Phase0 starts after the
// H0 wait (~half the copy), hiding ~1us/iter of staging.
// ---------------------------------------------------------------------------

#define MAXN       430000
#define MAXSLOT    16
#define MAXQUAD    4
#define TPB        1024
#define DPT        3
#define SMEM_BYTES 200704
#define MAXIT      33          // 0..30 iter barriers, 31 wide-zero, 32 prep
#define MAXB       16

__device__ float g_w[(size_t)MAXN * MAXSLOT];     // exact softmax weights (epilogue)
__device__ uint4 g_eq[(size_t)2 * MAXQUAD * MAXN];// packed (rows 0..3) / wide fmt
__device__ int   g_maxcnt;
__device__ unsigned g_ctr[MAXIT * MAXB * 32];     // 128B-strided counters
__device__ __align__(16) __half g_xa[MAXN];
__device__ __align__(16) __half g_xb[MAXN];

__device__ __forceinline__ unsigned smem_u32(const void* p) {
    unsigned r;
    asm("{ .reg .u64 t; cvta.to.shared.u64 t, %1; cvt.u32.u64 %0, t; }"
        : "=r"(r) : "l"(p));
    return r;
}

__device__ __forceinline__ void mbar_wait(unsigned mb, unsigned parity) {
    unsigned done;
    do {
        asm volatile("{ .reg .pred p; "
                     "mbarrier.try_wait.parity.acquire.cta.shared::cta.b64 p, [%1], %2, 0x989680; "
                     "selp.b32 %0, 1, 0, p; }"
                     : "=r"(done) : "r"(mb), "r"(parity) : "memory");
    } while (!done);
}

// cg-style grid barrier
__device__ __forceinline__ void bar_sync(unsigned* ctr, unsigned expect) {
    __syncthreads();
    if (threadIdx.x == 0) {
        unsigned v;
        asm volatile("atom.add.release.gpu.u32 %0, [%1], 1;"
                     : "=r"(v) : "l"(ctr) : "memory");
        do {
            asm volatile("ld.acquire.gpu.u32 %0, [%1];"
                         : "=r"(v) : "l"(ctr) : "memory");
        } while (v < expect);
        asm volatile("fence.proxy.async;" ::: "memory");
    }
    __syncthreads();
}

// unpredicated quad
#define EDGE4(E, ACC)                                                          \
    do {                                                                       \
        ACC = fmaf(__uint2float_rn((E).x >> 17), __half2float(xh[(E).x & 0x1FFFFu]), ACC); \
        ACC = fmaf(__uint2float_rn((E).y >> 17), __half2float(xh[(E).y & 0x1FFFFu]), ACC); \
        ACC = fmaf(__uint2float_rn((E).z >> 17), __half2float(xh[(E).z & 0x1FFFFu]), ACC); \
        ACC = fmaf(__uint2float_rn((E).w >> 17), __half2float(xh[(E).w & 0x1FFFFu]), ACC); \
    } while (0)

// predicated single edge: process iff (idx < H) == LOW
#define EDGE1P(U, ACC, H, LOW)                                                 \
    do {                                                                       \
        unsigned _i = (U) & 0x1FFFFu;                                          \
        if (((_i < (H)) ? 1 : 0) == (LOW))                                     \
            ACC = fmaf(__uint2float_rn((U) >> 17), __half2float(xh[_i]), ACC); \
    } while (0)

#define EDGE4P(E, ACC, H, LOW)                                                 \
    do {                                                                       \
        EDGE1P((E).x, ACC, H, LOW);                                            \
        EDGE1P((E).y, ACC, H, LOW);                                            \
        EDGE1P((E).z, ACC, H, LOW);                                            \
        EDGE1P((E).w, ACC, H, LOW);                                            \
    } while (0)

// --- everything in one persistent kernel ------------------------------------
__global__ void __launch_bounds__(TPB, 1) k_all(const float* __restrict__ fp,
                                                const int*   __restrict__ adj,
                                                const float* __restrict__ dem,
                                                float*       __restrict__ out,
                                                int BN, int D, int niter,
                                                const int* __restrict__ num_nodes) {
    extern __shared__ unsigned char xs[];
    __shared__ __align__(8) unsigned long long mbar0, mbar1;

    const int N    = __ldg(num_nodes);
    const int B    = BN / N;
    const int bpb  = gridDim.x / B;
    const unsigned nblk = (unsigned)(bpb * B);
    const int blk  = blockIdx.x;
    if (blk >= (int)nblk) return;
    const int b     = blk / bpb;
    const int ib    = blk - b * bpb;
    const int spb   = (N + bpb - 1) / bpb;
    const int start = b * N + ib * spb;
    const int stop  = min(start + spb, (b + 1) * N);

    const unsigned bytes = (unsigned)N * 2u;
    const bool whole   = (bytes <= SMEM_BYTES);
    const bool bulk_ok = whole && ((bytes & 15u) == 0u);

    const unsigned h0 = ((unsigned)(N / 2) + 7u) & ~7u;    // H0 element count (16B-aligned bytes)
    const bool split_ok = bulk_ok && (h0 > 0) && (h0 < (unsigned)N);

    const int grp = (B <= MAXB) ? b : 0;
    const unsigned expect = (B <= MAXB) ? (unsigned)bpb : nblk;

    const unsigned mb0 = smem_u32(&mbar0);
    const unsigned mb1 = smem_u32(&mbar1);
    if (threadIdx.x == 0) {
        asm volatile("mbarrier.init.shared.b64 [%0], %1;" :: "r"(mb0), "r"(1) : "memory");
        asm volatile("mbarrier.init.shared.b64 [%0], %1;" :: "r"(mb1), "r"(1) : "memory");
    }

    // !whole: zero wide-format weight rows in-kernel
    if (!whole) {
        uint4 z = make_uint4(0, 0, 0, 0);
        const size_t tot = (size_t)MAXQUAD * BN;
        for (size_t i = (size_t)blk * TPB + threadIdx.x; i < tot;
             i += (size_t)nblk * TPB)
            g_eq[(size_t)MAXQUAD * BN + i] = z;
        bar_sync(&g_ctr[(MAXIT - 2) * MAXB * 32], nblk);
    }

    // ======================= PHASE A: prep =================================
    {
        const int gstride = (int)nblk * TPB;
        int maxd = 0;
        unsigned* e1 = (unsigned*)g_eq;

        for (int t = blk * TPB + threadIdx.x; t < BN; t += gstride) {
            const int bb   = t / N;
            const int base = bb * N;
            const int u    = t - base;

            float e[MAXSLOT];
            int   a[MAXSLOT];
            float sum = 0.f;
            if (D == MAXSLOT) {
                const float4* f4 = (const float4*)(fp + (size_t)t * MAXSLOT);
                const int4*   a4 = (const int4*)(adj + (size_t)t * MAXSLOT);
#pragma unroll
                for (int g = 0; g < 4; ++g) {
                    int4 av = __ldg(a4 + g);
                    a[4*g+0] = av.x; a[4*g+1] = av.y; a[4*g+2] = av.z; a[4*g+3] = av.w;
                    if ((av.x != N) | (av.y != N) | (av.z != N) | (av.w != N)) {
                        float4 f = __ldg(f4 + g);
                        e[4*g+0] = (av.x == N) ? 0.f : __expf(f.x);
                        e[4*g+1] = (av.y == N) ? 0.f : __expf(f.y);
                        e[4*g+2] = (av.z == N) ? 0.f : __expf(f.z);
                        e[4*g+3] = (av.w == N) ? 0.f : __expf(f.w);
                        sum += e[4*g+0] + e[4*g+1] + e[4*g+2] + e[4*g+3];
                    } else {
                        e[4*g+0] = e[4*g+1] = e[4*g+2] = e[4*g+3] = 0.f;
                    }
                }
            } else {
                for (int d = 0; d < D; ++d) {
                    a[d] = __ldg(adj + (size_t)t * D + d);
                    float f = __ldg(fp + (size_t)t * D + d);
                    e[d] = (a[d] == N) ? 0.f : __expf(f);
                    sum += e[d];
                }
            }
            const float inv = 1.f / sum;

            if (D == MAXSLOT) {
                float4* w4 = (float4*)(g_w + (size_t)t * MAXSLOT);
#pragma unroll
                for (int g = 0; g < 4; ++g)
                    w4[g] = make_float4(e[4*g+0]*inv, e[4*g+1]*inv,
                                        e[4*g+2]*inv, e[4*g+3]*inv);
            } else {
                for (int d = 0; d < D; ++d)
                    g_w[(size_t)t * D + d] = e[d] * inv;
            }

            for (int d = 0; d < D; ++d) {
                if (a[d] != N) {
                    const int v = base + a[d];
                    const int q = d >> 2;
                    const float w = e[d] * inv;
                    const size_t lane = (((size_t)q * BN + v) << 2) + (d & 3);
                    if (whole) {
                        unsigned wq = (unsigned)(w * 32767.f + 0.5f);
                        if (wq > 32767u) wq = 32767u;
                        e1[lane] = (unsigned)u | (wq << 17);
                    } else {
                        e1[lane] = (unsigned)u;
                        e1[(((size_t)(MAXQUAD + q) * BN + v) << 2) + (d & 3)] =
                            __float_as_uint(w);
                    }
                    maxd = max(maxd, d + 1);
                }
            }
        }
        maxd = __reduce_max_sync(0xffffffffu, maxd);
        if ((threadIdx.x & 31) == 0 && maxd > 0) atomicMax(&g_maxcnt, maxd);
    }

    bar_sync(&g_ctr[(MAXIT - 1) * MAXB * 32], nblk);   // global prep barrier

    const int Q = (*(volatile int*)&g_maxcnt + 3) >> 2;

    float dm[DPT];
    int   dl[DPT];
#pragma unroll
    for (int k = 0; k < DPT; ++k) {
        int d = start + threadIdx.x + k * TPB;
        dl[k] = min(d, stop - 1);
        dm[k] = (d < stop) ? __ldg(dem + d) : 0.f;
    }

    const __half* xh = (const __half*)xs;
    const float INV15 = 1.0f / 32767.0f;
    const bool fast3 = split_ok && (Q == 3);

    // ======================= PHASE B: iterations ============================
    for (int it = 0; it < niter; ++it) {
        float r_out[DPT];

        if (it == 0) {
#pragma unroll
            for (int k = 0; k < DPT; ++k) r_out[k] = fmaxf(-dm[k], 0.f);
        } else {
            const __half* xo = (it & 1) ? g_xb : g_xa;
            const unsigned par = (unsigned)((it + 1) & 1);   // it=1 -> parity 0

            if (bulk_ok && threadIdx.x == 0) {
                if (fast3) {
                    const unsigned sz0 = h0 * 2u;
                    const unsigned sz1 = bytes - sz0;
                    asm volatile("mbarrier.arrive.expect_tx.shared.b64 _, [%0], %1;"
                                 :: "r"(mb0), "r"(sz0) : "memory");
                    asm volatile("cp.async.bulk.shared::cta.global.mbarrier::complete_tx::bytes "
                                 "[%0], [%1], %2, [%3];"
                                 :: "r"(smem_u32(xs)), "l"(xo + (size_t)b * N),
                                    "r"(sz0), "r"(mb0)
                                 : "memory");
                    asm volatile("mbarrier.arrive.expect_tx.shared.b64 _, [%0], %1;"
                                 :: "r"(mb1), "r"(sz1) : "memory");
                    asm volatile("cp.async.bulk.shared::cta.global.mbarrier::complete_tx::bytes "
                                 "[%0], [%1], %2, [%3];"
                                 :: "r"(smem_u32(xs) + sz0),
                                    "l"(xo + (size_t)b * N + h0),
                                    "r"(sz1), "r"(mb1)
                                 : "memory");
                } else {
                    asm volatile("mbarrier.arrive.expect_tx.shared.b64 _, [%0], %1;"
                                 :: "r"(mb0), "r"(bytes) : "memory");
                    asm volatile("cp.async.bulk.shared::cta.global.mbarrier::complete_tx::bytes "
                                 "[%0], [%1], %2, [%3];"
                                 :: "r"(smem_u32(xs)), "l"(xo + (size_t)b * N),
                                    "r"(bytes), "r"(mb0)
                                 : "memory");
                }
            }

            if (fast3) {
                // ---- prefetch all 9 edge quads before any wait --------------
                uint4 EQ[DPT][3];
#pragma unroll
                for (int k = 0; k < DPT; ++k) {
                    const uint4* ep = g_eq + dl[k];
                    EQ[k][0] = __ldcg(ep);
                    EQ[k][1] = __ldcg(ep + BN);
                    EQ[k][2] = __ldcg(ep + 2 * (size_t)BN);
                }

                float acc[DPT];
#pragma unroll
                for (int k = 0; k < DPT; ++k) acc[k] = 0.f;

                // ---- phase 0: sources in H0 (idx < h0) -----------------------
                mbar_wait(mb0, par);
#pragma unroll
                for (int k = 0; k < DPT; ++k) {
                    EDGE4P(EQ[k][0], acc[k], h0, 1);
                    EDGE4P(EQ[k][1], acc[k], h0, 1);
                    EDGE4P(EQ[k][2], acc[k], h0, 1);
                }

                // ---- phase 1: sources in H1 (idx >= h0) ----------------------
                mbar_wait(mb1, par);
#pragma unroll
                for (int k = 0; k < DPT; ++k) {
                    EDGE4P(EQ[k][0], acc[k], h0, 0);
                    EDGE4P(EQ[k][1], acc[k], h0, 0);
                    EDGE4P(EQ[k][2], acc[k], h0, 0);
                    r_out[k] = fmaxf(fmaf(acc[k], INV15, -dm[k]), 0.f);
                }
            } else if (whole) {
                // ---- generic runtime-Q path (single copy, mb0) ---------------
                uint4 e0[DPT];
#pragma unroll
                for (int k = 0; k < DPT; ++k)
                    e0[k] = __ldcg(&g_eq[dl[k]]);

                if (!bulk_ok) {
                    __half* dh = (__half*)xs;
                    for (int i = threadIdx.x; i < N; i += TPB)
                        dh[i] = __ldcg(xo + (size_t)b * N + i);
                    __syncthreads();
                } else {
                    mbar_wait(mb0, par);
                }

#pragma unroll
                for (int k = 0; k < DPT; ++k) {
                    const uint4* ep = g_eq + dl[k];
                    float a = 0.f;
                    uint4 e = e0[k];
#pragma unroll 3
                    for (int q = 1; q < Q; ++q) {
                        uint4 f = __ldcg(ep + (size_t)q * BN);
                        EDGE4(e, a);
                        e = f;
                    }
                    EDGE4(e, a);
                    r_out[k] = fmaxf(fmaf(a, INV15, -dm[k]), 0.f);
                }
            } else {
                // giant-N fallback
                const __half* xob = xo + (size_t)b * N;
#pragma unroll
                for (int k = 0; k < DPT; ++k) {
                    const uint4* ep = g_eq + dl[k];
                    float a = 0.f;
                    for (int q = 0; q < Q; ++q) {
                        uint4 fs = __ldcg(ep + (size_t)q * BN);
                        uint4 wb = __ldcg(ep + (size_t)(MAXQUAD + q) * BN);
                        a = fmaf(__uint_as_float(wb.x), __half2float(__ldcg(xob + fs.x)), a);
                        a = fmaf(__uint_as_float(wb.y), __half2float(__ldcg(xob + fs.y)), a);
                        a = fmaf(__uint_as_float(wb.z), __half2float(__ldcg(xob + fs.z)), a);
                        a = fmaf(__uint_as_float(wb.w), __half2float(__ldcg(xob + fs.w)), a);
                    }
                    r_out[k] = fmaxf(a - dm[k], 0.f);
                }
            }
        }

        if (it == niter - 1) {
            // ---- fused epilogue: out[d,:] = g_w[d,:] * r (exact fp32 w) ------
            __syncthreads();
            float* rs = (float*)xs;
#pragma unroll
            for (int k = 0; k < DPT; ++k) {
                int d = start + threadIdx.x + k * TPB;
                if (d < stop) rs[d - start] = r_out[k];
            }
            __syncthreads();
            const int rows = stop - start;
            if ((D & 3) == 0) {
                const int dq = D >> 2;
                const int total4 = rows * dq;
                const float4* w4 = (const float4*)(g_w + (size_t)start * D);
                float4*       o4 = (float4*)(out + (size_t)start * D);
                for (int i = threadIdx.x; i < total4; i += TPB) {
                    float4 w = __ldcg(w4 + i);
                    float  r = rs[i / dq];
                    o4[i] = make_float4(w.x * r, w.y * r, w.z * r, w.w * r);
                }
            } else {
                const int total = rows * D;
                for (int i = threadIdx.x; i < total; i += TPB)
                    out[(size_t)start * D + i] = g_w[(size_t)start * D + i] * rs[i / D];
            }
        } else {
            __half* xn = (it & 1) ? g_xa : g_xb;
#pragma unroll
            for (int k = 0; k < DPT; ++k) {
                int d = start + threadIdx.x + k * TPB;
                if (d < stop) xn[d] = __float2half_rn(r_out[k]);
            }
            bar_sync(&g_ctr[(it * MAXB + grp) * 32], expect);
        }
    }
}

extern "C" void kernel_launch(void* const* d_in, const int* in_sizes, int n_in,
                              void* d_out, int out_size) {
    const float* fp  = (const float*)d_in[0];
    const float* dem = (const float*)d_in[1];
    const int*   adj = (const int*)d_in[2];
    const int*   nn  = (const int*)d_in[4];

    const int E  = in_sizes[0];
    const int BN = in_sizes[1];
    const int D  = E / BN;
    const int NITER = 32;

    void *pe, *pmc, *pct;
    cudaGetSymbolAddress(&pe, g_eq);
    cudaGetSymbolAddress(&pmc, g_maxcnt);
    cudaGetSymbolAddress(&pct, g_ctr);

    int sm = 148;
    cudaDeviceGetAttribute(&sm, cudaDevAttrMultiProcessorCount, 0);

    cudaFuncSetAttribute(k_all, cudaFuncAttributeMaxDynamicSharedMemorySize,
                         SMEM_BYTES);

    // packed rows only; wide weight rows zeroed in-kernel when needed
    const size_t ebytes = (size_t)MAXQUAD * BN * sizeof(uint4);
    cudaMemsetAsync(pe, 0, ebytes, 0);
    cudaMemsetAsync(pmc, 0, sizeof(int), 0);
    cudaMemsetAsync(pct, 0, sizeof(unsigned) * MAXIT * MAXB * 32, 0);

    // plain persistent launch: 1 block/SM, all resident => barriers safe
    k_all<<<sm, TPB, SMEM_BYTES>>>(fp, adj, dem, (float*)d_out, BN, D, NITER, nn);
}

// round 17
// speedup vs baseline: 2.5029x; 2.5029x over previous
#include <cuda_runtime.h>
#include <cuda_fp16.h>
#include <cstdint>

// ---------------------------------------------------------------------------
// x_{k+1}[v] = relu( sum_d W[v,d]*x_k[src[v,d]] - demand[v] ), 32 iters,
// out = weights * x_32.  B=4, N=100K, D=16 (12 valid).
//
// R17 = R15 (best structure: Q==3 unrolled uniform walk, 9-quad prefetch,
// quantized 4B edges, TMA staging, per-batch barriers, fused epilogue) +
//  (1) next iteration's TMA copy issued INSIDE the barrier by thread0
//      (right after its acquire-spin + proxy fence, before block release);
//  (2) one-time ~3us phase stagger for odd batches so batch copies overlap
//      other batches' walks instead of bursting the LTS together.
// ---------------------------------------------------------------------------

#define MAXN       430000
#define MAXSLOT    16
#define MAXQUAD    4
#define TPB        1024
#define DPT        3
#define SMEM_BYTES 200704
#define MAXIT      33          // 0..30 iter barriers, 31 wide-zero, 32 prep
#define MAXB       16
#define STAGGER_CYC 6000

__device__ float g_w[(size_t)MAXN * MAXSLOT];     // exact softmax weights (epilogue)
__device__ uint4 g_eq[(size_t)2 * MAXQUAD * MAXN];// packed (rows 0..3) / wide fmt
__device__ int   g_maxcnt;
__device__ unsigned g_ctr[MAXIT * MAXB * 32];     // 128B-strided counters
__device__ __align__(16) __half g_xa[MAXN];
__device__ __align__(16) __half g_xb[MAXN];

__device__ __forceinline__ unsigned smem_u32(const void* p) {
    unsigned r;
    asm("{ .reg .u64 t; cvta.to.shared.u64 t, %1; cvt.u32.u64 %0, t; }"
        : "=r"(r) : "l"(p));
    return r;
}

__device__ __forceinline__ void mbar_wait(unsigned mb, unsigned parity) {
    unsigned done;
    do {
        asm volatile("{ .reg .pred p; "
                     "mbarrier.try_wait.parity.acquire.cta.shared::cta.b64 p, [%1], %2, 0x989680; "
                     "selp.b32 %0, 1, 0, p; }"
                     : "=r"(done) : "r"(mb), "r"(parity) : "memory");
    } while (!done);
}

// grid barrier; thread0 issues next iteration's bulk copy after the spin,
// before releasing the block (copy overlaps release + edge prefetch).
__device__ __forceinline__ void bar_sync_copy(unsigned* ctr, unsigned expect,
                                              bool do_copy, unsigned mb,
                                              unsigned smem_dst,
                                              const __half* src, unsigned bytes) {
    __syncthreads();                           // all warps done with xs + stores
    if (threadIdx.x == 0) {
        unsigned v;
        asm volatile("atom.add.release.gpu.u32 %0, [%1], 1;"
                     : "=r"(v) : "l"(ctr) : "memory");
        do {
            asm volatile("ld.acquire.gpu.u32 %0, [%1];"
                         : "=r"(v) : "l"(ctr) : "memory");
        } while (v < expect);
        asm volatile("fence.proxy.async;" ::: "memory");
        if (do_copy) {
            asm volatile("mbarrier.arrive.expect_tx.shared.b64 _, [%0], %1;"
                         :: "r"(mb), "r"(bytes) : "memory");
            asm volatile("cp.async.bulk.shared::cta.global.mbarrier::complete_tx::bytes "
                         "[%0], [%1], %2, [%3];"
                         :: "r"(smem_dst), "l"(src), "r"(bytes), "r"(mb)
                         : "memory");
        }
    }
    __syncthreads();
}

// unpredicated quad: 4 edges of (idx:17 | wq:15)
#define EDGE4(E, ACC)                                                          \
    do {                                                                       \
        ACC = fmaf(__uint2float_rn((E).x >> 17), __half2float(xh[(E).x & 0x1FFFFu]), ACC); \
        ACC = fmaf(__uint2float_rn((E).y >> 17), __half2float(xh[(E).y & 0x1FFFFu]), ACC); \
        ACC = fmaf(__uint2float_rn((E).z >> 17), __half2float(xh[(E).z & 0x1FFFFu]), ACC); \
        ACC = fmaf(__uint2float_rn((E).w >> 17), __half2float(xh[(E).w & 0x1FFFFu]), ACC); \
    } while (0)

// --- everything in one persistent kernel ------------------------------------
__global__ void __launch_bounds__(TPB, 1) k_all(const float* __restrict__ fp,
                                                const int*   __restrict__ adj,
                                                const float* __restrict__ dem,
                                                float*       __restrict__ out,
                                                int BN, int D, int niter,
                                                const int* __restrict__ num_nodes) {
    extern __shared__ unsigned char xs[];
    __shared__ __align__(8) unsigned long long mbar;

    const int N    = __ldg(num_nodes);
    const int B    = BN / N;
    const int bpb  = gridDim.x / B;
    const unsigned nblk = (unsigned)(bpb * B);
    const int blk  = blockIdx.x;
    if (blk >= (int)nblk) return;
    const int b     = blk / bpb;
    const int ib    = blk - b * bpb;
    const int spb   = (N + bpb - 1) / bpb;
    const int start = b * N + ib * spb;
    const int stop  = min(start + spb, (b + 1) * N);

    const unsigned bytes = (unsigned)N * 2u;
    const bool whole   = (bytes <= SMEM_BYTES);
    const bool bulk_ok = whole && ((bytes & 15u) == 0u);

    const int grp = (B <= MAXB) ? b : 0;
    const unsigned expect = (B <= MAXB) ? (unsigned)bpb : nblk;

    const unsigned mb = smem_u32(&mbar);
    const unsigned xsa = smem_u32(xs);
    if (threadIdx.x == 0)
        asm volatile("mbarrier.init.shared.b64 [%0], %1;" :: "r"(mb), "r"(1) : "memory");

    // !whole: zero wide-format weight rows in-kernel
    if (!whole) {
        uint4 z = make_uint4(0, 0, 0, 0);
        const size_t tot = (size_t)MAXQUAD * BN;
        for (size_t i = (size_t)blk * TPB + threadIdx.x; i < tot;
             i += (size_t)nblk * TPB)
            g_eq[(size_t)MAXQUAD * BN + i] = z;
        bar_sync_copy(&g_ctr[(MAXIT - 2) * MAXB * 32], nblk, false, 0, 0, 0, 0);
    }

    // ======================= PHASE A: prep =================================
    {
        const int gstride = (int)nblk * TPB;
        int maxd = 0;
        unsigned* e1 = (unsigned*)g_eq;

        for (int t = blk * TPB + threadIdx.x; t < BN; t += gstride) {
            const int bb   = t / N;
            const int base = bb * N;
            const int u    = t - base;

            float e[MAXSLOT];
            int   a[MAXSLOT];
            float sum = 0.f;
            if (D == MAXSLOT) {
                const float4* f4 = (const float4*)(fp + (size_t)t * MAXSLOT);
                const int4*   a4 = (const int4*)(adj + (size_t)t * MAXSLOT);
#pragma unroll
                for (int g = 0; g < 4; ++g) {
                    int4 av = __ldg(a4 + g);
                    a[4*g+0] = av.x; a[4*g+1] = av.y; a[4*g+2] = av.z; a[4*g+3] = av.w;
                    if ((av.x != N) | (av.y != N) | (av.z != N) | (av.w != N)) {
                        float4 f = __ldg(f4 + g);
                        e[4*g+0] = (av.x == N) ? 0.f : __expf(f.x);
                        e[4*g+1] = (av.y == N) ? 0.f : __expf(f.y);
                        e[4*g+2] = (av.z == N) ? 0.f : __expf(f.z);
                        e[4*g+3] = (av.w == N) ? 0.f : __expf(f.w);
                        sum += e[4*g+0] + e[4*g+1] + e[4*g+2] + e[4*g+3];
                    } else {
                        e[4*g+0] = e[4*g+1] = e[4*g+2] = e[4*g+3] = 0.f;
                    }
                }
            } else {
                for (int d = 0; d < D; ++d) {
                    a[d] = __ldg(adj + (size_t)t * D + d);
                    float f = __ldg(fp + (size_t)t * D + d);
                    e[d] = (a[d] == N) ? 0.f : __expf(f);
                    sum += e[d];
                }
            }
            const float inv = 1.f / sum;

            if (D == MAXSLOT) {
                float4* w4 = (float4*)(g_w + (size_t)t * MAXSLOT);
#pragma unroll
                for (int g = 0; g < 4; ++g)
                    w4[g] = make_float4(e[4*g+0]*inv, e[4*g+1]*inv,
                                        e[4*g+2]*inv, e[4*g+3]*inv);
            } else {
                for (int d = 0; d < D; ++d)
                    g_w[(size_t)t * D + d] = e[d] * inv;
            }

            for (int d = 0; d < D; ++d) {
                if (a[d] != N) {
                    const int v = base + a[d];
                    const int q = d >> 2;
                    const float w = e[d] * inv;
                    const size_t lane = (((size_t)q * BN + v) << 2) + (d & 3);
                    if (whole) {
                        unsigned wq = (unsigned)(w * 32767.f + 0.5f);
                        if (wq > 32767u) wq = 32767u;
                        e1[lane] = (unsigned)u | (wq << 17);
                    } else {
                        e1[lane] = (unsigned)u;
                        e1[(((size_t)(MAXQUAD + q) * BN + v) << 2) + (d & 3)] =
                            __float_as_uint(w);
                    }
                    maxd = max(maxd, d + 1);
                }
            }
        }
        maxd = __reduce_max_sync(0xffffffffu, maxd);
        if ((threadIdx.x & 31) == 0 && maxd > 0) atomicMax(&g_maxcnt, maxd);
    }

    bar_sync_copy(&g_ctr[(MAXIT - 1) * MAXB * 32], nblk, false, 0, 0, 0, 0);

    const int Q = (*(volatile int*)&g_maxcnt + 3) >> 2;

    float dm[DPT];
    int   dl[DPT];
#pragma unroll
    for (int k = 0; k < DPT; ++k) {
        int d = start + threadIdx.x + k * TPB;
        dl[k] = min(d, stop - 1);
        dm[k] = (d < stop) ? __ldg(dem + d) : 0.f;
    }

    const __half* xh = (const __half*)xs;
    const float INV15 = 1.0f / 32767.0f;
    const bool fast3 = bulk_ok && (Q == 3);

    // one-time phase stagger: odd batches delay ~3us so batch copies overlap
    // other batches' walks (LTS de-phasing). Pure delay: correctness-neutral.
    if (bulk_ok && B > 1 && (b & 1)) {
        if (threadIdx.x == 0) {
            long long t0 = clock64();
            while (clock64() - t0 < STAGGER_CYC) { }
        }
        __syncthreads();
    }

    // ======================= PHASE B: iterations ============================
    for (int it = 0; it < niter; ++it) {
        float r_out[DPT];

        if (it == 0) {
#pragma unroll
            for (int k = 0; k < DPT; ++k) r_out[k] = fmaxf(-dm[k], 0.f);
        } else {
            // copy for this iteration was issued inside the previous barrier
            const __half* xo = (it & 1) ? g_xb : g_xa;
            const unsigned par = (unsigned)((it + 1) & 1);   // it=1 -> parity 0

            if (fast3) {
                // ---- prefetch all 9 edge quads before the wait ---------------
                uint4 EQ[DPT][3];
#pragma unroll
                for (int k = 0; k < DPT; ++k) {
                    const uint4* ep = g_eq + dl[k];
                    EQ[k][0] = __ldcg(ep);
                    EQ[k][1] = __ldcg(ep + BN);
                    EQ[k][2] = __ldcg(ep + 2 * (size_t)BN);
                }

                mbar_wait(mb, par);

#pragma unroll
                for (int k = 0; k < DPT; ++k) {
                    float a = 0.f;
                    EDGE4(EQ[k][0], a);
                    EDGE4(EQ[k][1], a);
                    EDGE4(EQ[k][2], a);
                    r_out[k] = fmaxf(fmaf(a, INV15, -dm[k]), 0.f);
                }
            } else if (whole) {
                // ---- generic runtime-Q path ---------------------------------
                uint4 e0[DPT];
#pragma unroll
                for (int k = 0; k < DPT; ++k)
                    e0[k] = __ldcg(&g_eq[dl[k]]);

                if (!bulk_ok) {
                    __half* dh = (__half*)xs;
                    for (int i = threadIdx.x; i < N; i += TPB)
                        dh[i] = __ldcg(xo + (size_t)b * N + i);
                    __syncthreads();
                } else {
                    mbar_wait(mb, par);
                }

#pragma unroll
                for (int k = 0; k < DPT; ++k) {
                    const uint4* ep = g_eq + dl[k];
                    float a = 0.f;
                    uint4 e = e0[k];
#pragma unroll 3
                    for (int q = 1; q < Q; ++q) {
                        uint4 f = __ldcg(ep + (size_t)q * BN);
                        EDGE4(e, a);
                        e = f;
                    }
                    EDGE4(e, a);
                    r_out[k] = fmaxf(fmaf(a, INV15, -dm[k]), 0.f);
                }
            } else {
                // giant-N fallback
                const __half* xob = xo + (size_t)b * N;
#pragma unroll
                for (int k = 0; k < DPT; ++k) {
                    const uint4* ep = g_eq + dl[k];
                    float a = 0.f;
                    for (int q = 0; q < Q; ++q) {
                        uint4 fs = __ldcg(ep + (size_t)q * BN);
                        uint4 wb = __ldcg(ep + (size_t)(MAXQUAD + q) * BN);
                        a = fmaf(__uint_as_float(wb.x), __half2float(__ldcg(xob + fs.x)), a);
                        a = fmaf(__uint_as_float(wb.y), __half2float(__ldcg(xob + fs.y)), a);
                        a = fmaf(__uint_as_float(wb.z), __half2float(__ldcg(xob + fs.z)), a);
                        a = fmaf(__uint_as_float(wb.w), __half2float(__ldcg(xob + fs.w)), a);
                    }
                    r_out[k] = fmaxf(a - dm[k], 0.f);
                }
            }
        }

        if (it == niter - 1) {
            // ---- fused epilogue: out[d,:] = g_w[d,:] * r (exact fp32 w) ------
            __syncthreads();
            float* rs = (float*)xs;
#pragma unroll
            for (int k = 0; k < DPT; ++k) {
                int d = start + threadIdx.x + k * TPB;
                if (d < stop) rs[d - start] = r_out[k];
            }
            __syncthreads();
            const int rows = stop - start;
            if ((D & 3) == 0) {
                const int dq = D >> 2;
                const int total4 = rows * dq;
                const float4* w4 = (const float4*)(g_w + (size_t)start * D);
                float4*       o4 = (float4*)(out + (size_t)start * D);
                for (int i = threadIdx.x; i < total4; i += TPB) {
                    float4 w = __ldcg(w4 + i);
                    float  r = rs[i / dq];
                    o4[i] = make_float4(w.x * r, w.y * r, w.z * r, w.w * r);
                }
            } else {
                const int total = rows * D;
                for (int i = threadIdx.x; i < total; i += TPB)
                    out[(size_t)start * D + i] = g_w[(size_t)start * D + i] * rs[i / D];
            }
        } else {
            // write next x (fp16), then barrier + issue next copy inside it
            __half* xn = (it & 1) ? g_xa : g_xb;
#pragma unroll
            for (int k = 0; k < DPT; ++k) {
                int d = start + threadIdx.x + k * TPB;
                if (d < stop) xn[d] = __float2half_rn(r_out[k]);
            }
            // next iteration (it+1 >= 1) reads xn as its xo
            bar_sync_copy(&g_ctr[(it * MAXB + grp) * 32], expect,
                          bulk_ok, mb, xsa, xn + (size_t)b * N, bytes);
        }
    }
}

extern "C" void kernel_launch(void* const* d_in, const int* in_sizes, int n_in,
                              void* d_out, int out_size) {
    const float* fp  = (const float*)d_in[0];
    const float* dem = (const float*)d_in[1];
    const int*   adj = (const int*)d_in[2];
    const int*   nn  = (const int*)d_in[4];

    const int E  = in_sizes[0];
    const int BN = in_sizes[1];
    const int D  = E / BN;
    const int NITER = 32;

    void *pe, *pmc, *pct;
    cudaGetSymbolAddress(&pe, g_eq);
    cudaGetSymbolAddress(&pmc, g_maxcnt);
    cudaGetSymbolAddress(&pct, g_ctr);

    int sm = 148;
    cudaDeviceGetAttribute(&sm, cudaDevAttrMultiProcessorCount, 0);

    cudaFuncSetAttribute(k_all, cudaFuncAttributeMaxDynamicSharedMemorySize,
                         SMEM_BYTES);

    // packed rows only; wide weight rows zeroed in-kernel when needed
    const size_t ebytes = (size_t)MAXQUAD * BN * sizeof(uint4);
    cudaMemsetAsync(pe, 0, ebytes, 0);
    cudaMemsetAsync(pmc, 0, sizeof(int), 0);
    cudaMemsetAsync(pct, 0, sizeof(unsigned) * MAXIT * MAXB * 32, 0);

    // plain persistent launch: 1 block/SM, all resident => barriers safe
    k_all<<<sm, TPB, SMEM_BYTES>>>(fp, adj, dem, (float*)d_out, BN, D, NITER, nn);
}